// round 7
// baseline (speedup 1.0000x reference)
#include <cuda_runtime.h>
#include <cstdint>

#define BB 4
#define LQ 256
#define LK 256
#define DD 768

// Scratch (no cudaMalloc allowed)
__device__ float g_q[BB*LQ*DD];
__device__ float g_k[BB*LK*DD];
__device__ float g_v[BB*LK*DD];
__device__ float g_scores[BB*LQ*LK];
__device__ unsigned g_tile_ctr;

__device__ __forceinline__ float tanh_fast(float x) {
    float y;
    asm("tanh.approx.f32 %0, %1;" : "=f"(y) : "f"(x));
    return y;
}

// ---- tf32 helpers ----
__device__ __forceinline__ uint32_t f2tf32(float x) {
    uint32_t u;
    asm("cvt.rna.tf32.f32 %0, %1;" : "=r"(u) : "f"(x));
    return u;
}
__device__ __forceinline__ void mma_tf32(float& d0, float& d1, float& d2, float& d3,
                                         uint32_t a0, uint32_t a1, uint32_t a2, uint32_t a3,
                                         uint32_t b0, uint32_t b1) {
    asm("mma.sync.aligned.m16n8k8.row.col.f32.tf32.tf32.f32 "
        "{%0,%1,%2,%3}, {%4,%5,%6,%7}, {%8,%9}, {%0,%1,%2,%3};"
        : "+f"(d0), "+f"(d1), "+f"(d2), "+f"(d3)
        : "r"(a0), "r"(a1), "r"(a2), "r"(a3), "r"(b0), "r"(b1));
}

// ---------------------------------------------------------------------------
// Projection GEMM via tf32 mma. Out[M,N] = X[M,K] @ W[K,N] + b[N].
// 64x128 tile, 256 thr (2Mx4N warps), BK=32 double-buffered. (unchanged R6)
// ---------------------------------------------------------------------------
__global__ __launch_bounds__(256) void proj_kernel(
    const float* __restrict__ xq, const float* __restrict__ xk, const float* __restrict__ xv,
    const float* __restrict__ Wq, const float* __restrict__ bq,
    const float* __restrict__ Wk, const float* __restrict__ bk,
    const float* __restrict__ Wv, const float* __restrict__ bv)
{
    const int N = DD, K = DD;
    const float *X, *W, *bias;
    float* Out;
    if (blockIdx.z == 0)      { X = xq; W = Wq; bias = bq; Out = g_q; }
    else if (blockIdx.z == 1) { X = xk; W = Wk; bias = bk; Out = g_k; }
    else                      { X = xv; W = Wv; bias = bv; Out = g_v; }

    __shared__ uint32_t As[2][64][36];
    __shared__ uint32_t Bsm[2][32][136];

    const int t    = threadIdx.x;
    const int wid  = t >> 5;
    const int lane = t & 31;
    const int wm   = wid & 1;
    const int wn   = wid >> 1;
    const int grp  = lane >> 2;
    const int tig  = lane & 3;

    const int m0 = blockIdx.y * 64;
    const int n0 = blockIdx.x * 128;

    float acc[2][4][4];
    #pragma unroll
    for (int i = 0; i < 2; i++)
        #pragma unroll
        for (int j = 0; j < 4; j++)
            #pragma unroll
            for (int r = 0; r < 4; r++) acc[i][j][r] = 0.f;

    const int ar = t >> 2, ac = (t & 3) * 8;
    const int br = t >> 3, bc = (t & 7) * 16;

    const float* Xp = X + (size_t)(m0 + ar) * K + ac;
    const float* Wp = W + (size_t)br * N + n0 + bc;

    float4 pa0 = *(const float4*)(Xp);
    float4 pa1 = *(const float4*)(Xp + 4);
    float4 pb[4];
    #pragma unroll
    for (int u = 0; u < 4; u++) pb[u] = *(const float4*)(Wp + u*4);

    int buf = 0;
    for (int k0 = 0; k0 < K; k0 += 32) {
        {
            uint4 ua0 = { f2tf32(pa0.x), f2tf32(pa0.y), f2tf32(pa0.z), f2tf32(pa0.w) };
            uint4 ua1 = { f2tf32(pa1.x), f2tf32(pa1.y), f2tf32(pa1.z), f2tf32(pa1.w) };
            *(uint4*)&As[buf][ar][ac]     = ua0;
            *(uint4*)&As[buf][ar][ac + 4] = ua1;
            #pragma unroll
            for (int u = 0; u < 4; u++) {
                uint4 ub = { f2tf32(pb[u].x), f2tf32(pb[u].y), f2tf32(pb[u].z), f2tf32(pb[u].w) };
                *(uint4*)&Bsm[buf][br][bc + u*4] = ub;
            }
        }
        __syncthreads();

        if (k0 + 32 < K) {
            pa0 = *(const float4*)(Xp + k0 + 32);
            pa1 = *(const float4*)(Xp + k0 + 36);
            const float* wpn = Wp + (size_t)(k0 + 32) * N;
            #pragma unroll
            for (int u = 0; u < 4; u++) pb[u] = *(const float4*)(wpn + u*4);
        }

        #pragma unroll
        for (int ks = 0; ks < 4; ks++) {
            const int kb = ks * 8;
            uint32_t a[2][4];
            #pragma unroll
            for (int mi = 0; mi < 2; mi++) {
                const int mb = wm*32 + mi*16;
                a[mi][0] = As[buf][mb + grp    ][kb + tig];
                a[mi][1] = As[buf][mb + grp + 8][kb + tig];
                a[mi][2] = As[buf][mb + grp    ][kb + tig + 4];
                a[mi][3] = As[buf][mb + grp + 8][kb + tig + 4];
            }
            uint32_t b[4][2];
            #pragma unroll
            for (int ni = 0; ni < 4; ni++) {
                const int nb = wn*32 + ni*8;
                b[ni][0] = Bsm[buf][kb + tig    ][nb + grp];
                b[ni][1] = Bsm[buf][kb + tig + 4][nb + grp];
            }
            #pragma unroll
            for (int mi = 0; mi < 2; mi++)
                #pragma unroll
                for (int ni = 0; ni < 4; ni++)
                    mma_tf32(acc[mi][ni][0], acc[mi][ni][1], acc[mi][ni][2], acc[mi][ni][3],
                             a[mi][0], a[mi][1], a[mi][2], a[mi][3],
                             b[ni][0], b[ni][1]);
        }
        __syncthreads();
        buf ^= 1;
    }

    #pragma unroll
    for (int mi = 0; mi < 2; mi++) {
        #pragma unroll
        for (int ni = 0; ni < 4; ni++) {
            const int col = n0 + wn*32 + ni*8 + 2*tig;
            const float b0 = bias[col], b1 = bias[col+1];
            const int r0 = m0 + wm*32 + mi*16 + grp;
            const int r1 = r0 + 8;
            float2 lo = { acc[mi][ni][0] + b0, acc[mi][ni][1] + b1 };
            float2 hi = { acc[mi][ni][2] + b0, acc[mi][ni][3] + b1 };
            *(float2*)&Out[(size_t)r0 * N + col] = lo;
            *(float2*)&Out[(size_t)r1 * N + col] = hi;
        }
    }
}

// ---------------------------------------------------------------------------
// Scores: s[b,i,j] = sum_d Ws[d]*tanh(q[b,i,d]+k[b,j,d]) + bs.  MUFU-bound.
// Persistent blocks (296) pull 512 tiles (16q x 32k) from a global counter
// for near-perfect MUFU load balance. Ws cached in smem once per block.
// ---------------------------------------------------------------------------
#define SC_NT   512          // (LQ/16)*(LK/32)*BB
__global__ __launch_bounds__(256) void score_kernel(const float* __restrict__ Ws,
                                                    const float* __restrict__ bsp)
{
    __shared__ float Wsm[DD];
    __shared__ float Qs[16][65];
    __shared__ float Ks[32][65];
    __shared__ unsigned s_tile;

    const int t  = threadIdx.x;
    const int tx = t & 15;     // k pair: tx*2, tx*2+1
    const int ty = t >> 4;     // q row 0..15

    // cache Ws once
    for (int i = t; i < DD/4; i += 256)
        *(float4*)&Wsm[i*4] = *(const float4*)&Ws[i*4];
    const float bsv = *bsp;

    const int qr = t >> 4, qc = (t & 15) * 4;  // Q chunk load: 16 x 64
    const int kr = t >> 3, kc = (t & 7) * 8;   // K chunk load: 32 x 64

    for (;;) {
        __syncthreads();                       // protect s_tile + smem reuse
        if (t == 0) s_tile = atomicAdd(&g_tile_ctr, 1u);
        __syncthreads();
        const unsigned tile = s_tile;
        if (tile >= SC_NT) break;

        const int bz  = tile >> 7;             // 128 tiles per batch
        const int rem = tile & 127;
        const int q0  = (rem >> 3) * 16;
        const int k0  = (rem & 7) * 32;

        const float* qb = g_q + ((size_t)bz*LQ + q0) * DD;
        const float* kb = g_k + ((size_t)bz*LK + k0) * DD;

        float acc0 = 0.f, acc1 = 0.f;

        for (int d0 = 0; d0 < DD; d0 += 64) {
            float4 xq4 = *(const float4*)&qb[(size_t)qr*DD + d0 + qc];
            float4 y0  = *(const float4*)&kb[(size_t)kr*DD + d0 + kc];
            float4 y1  = *(const float4*)&kb[(size_t)kr*DD + d0 + kc + 4];
            Qs[qr][qc+0] = xq4.x; Qs[qr][qc+1] = xq4.y;
            Qs[qr][qc+2] = xq4.z; Qs[qr][qc+3] = xq4.w;
            Ks[kr][kc+0] = y0.x; Ks[kr][kc+1] = y0.y;
            Ks[kr][kc+2] = y0.z; Ks[kr][kc+3] = y0.w;
            Ks[kr][kc+4] = y1.x; Ks[kr][kc+5] = y1.y;
            Ks[kr][kc+6] = y1.z; Ks[kr][kc+7] = y1.w;
            __syncthreads();

            #pragma unroll 16
            for (int d = 0; d < 64; d++) {
                const float w  = Wsm[d0 + d];
                const float qa = Qs[ty][d];
                const float ka = Ks[tx*2+0][d];
                const float kc2 = Ks[tx*2+1][d];
                acc0 = fmaf(w, tanh_fast(qa + ka),  acc0);
                acc1 = fmaf(w, tanh_fast(qa + kc2), acc1);
            }
            __syncthreads();
        }

        float* sp = g_scores + ((size_t)bz*LQ + q0 + ty) * LK + k0;
        float2 r = { acc0 + bsv, acc1 + bsv };
        *(float2*)&sp[tx*2] = r;
    }
}

// ---------------------------------------------------------------------------
// Row softmax over LK=256. One block (256 threads) per (b,q) row.
// ---------------------------------------------------------------------------
__global__ __launch_bounds__(256) void softmax_kernel(float* __restrict__ wout)
{
    const int row = blockIdx.x;
    const int t   = threadIdx.x;
    __shared__ float red[8];

    const float v = g_scores[(size_t)row*LK + t];

    float m = v;
    #pragma unroll
    for (int o = 16; o > 0; o >>= 1) m = fmaxf(m, __shfl_xor_sync(0xffffffffu, m, o));
    if ((t & 31) == 0) red[t >> 5] = m;
    __syncthreads();
    float mx = red[0];
    #pragma unroll
    for (int i = 1; i < 8; i++) mx = fmaxf(mx, red[i]);
    __syncthreads();

    const float e = __expf(v - mx);
    float s = e;
    #pragma unroll
    for (int o = 16; o > 0; o >>= 1) s += __shfl_xor_sync(0xffffffffu, s, o);
    if ((t & 31) == 0) red[t >> 5] = s;
    __syncthreads();
    float sum = 0.f;
    #pragma unroll
    for (int i = 0; i < 8; i++) sum += red[i];

    wout[(size_t)row*LK + t] = e * (1.0f / sum);
}

// ---------------------------------------------------------------------------
// attended = weights @ v via tf32 mma: per batch, Out[256,768] = W[256,256]@V[256,768].
// Tile 32(M=q) x 128(N=d), 256 thr (8 warps: 1M x 8N, warp tile 32x16),
// BK=32 double-buffered. Grid (6, 8, 4) = 192 blocks.
// ---------------------------------------------------------------------------
__global__ __launch_bounds__(256) void av_kernel(const float* __restrict__ wts,
                                                 float* __restrict__ out)
{
    const int b  = blockIdx.z;
    const int q0 = blockIdx.y * 32;
    const int d0 = blockIdx.x * 128;

    __shared__ uint32_t As[2][32][36];     // weights [q][j] tf32
    __shared__ uint32_t Bsm[2][32][136];   // V [j][d] tf32

    const int t    = threadIdx.x;
    const int wid  = t >> 5;               // warp n-slot 0..7
    const int lane = t & 31;
    const int grp  = lane >> 2;
    const int tig  = lane & 3;

    float acc[2][2][4];                    // mi x ni x 4
    #pragma unroll
    for (int i = 0; i < 2; i++)
        #pragma unroll
        for (int j = 0; j < 2; j++)
            #pragma unroll
            for (int r = 0; r < 4; r++) acc[i][j][r] = 0.f;

    // A gmem load: 32 rows x 32 cols, 4 floats/thread
    const int ar = t >> 3, ac = (t & 7) * 4;
    // B gmem load: 32 rows x 128 cols, 16 floats/thread
    const int br = t >> 3, bc = (t & 7) * 16;

    const float* Ap = wts + ((size_t)b*LQ + q0 + ar) * LK + ac;
    const float* Bp = g_v + ((size_t)b*LK + br) * DD + d0 + bc;

    float4 pa = *(const float4*)(Ap);
    float4 pb[4];
    #pragma unroll
    for (int u = 0; u < 4; u++) pb[u] = *(const float4*)(Bp + u*4);

    int buf = 0;
    for (int j0 = 0; j0 < LK; j0 += 32) {
        {
            uint4 ua = { f2tf32(pa.x), f2tf32(pa.y), f2tf32(pa.z), f2tf32(pa.w) };
            *(uint4*)&As[buf][ar][ac] = ua;
            #pragma unroll
            for (int u = 0; u < 4; u++) {
                uint4 ub = { f2tf32(pb[u].x), f2tf32(pb[u].y), f2tf32(pb[u].z), f2tf32(pb[u].w) };
                *(uint4*)&Bsm[buf][br][bc + u*4] = ub;
            }
        }
        __syncthreads();

        if (j0 + 32 < LK) {
            pa = *(const float4*)(Ap + j0 + 32);
            const float* bpn = Bp + (size_t)(j0 + 32) * DD;
            #pragma unroll
            for (int u = 0; u < 4; u++) pb[u] = *(const float4*)(bpn + u*4);
        }

        #pragma unroll
        for (int ks = 0; ks < 4; ks++) {
            const int kb = ks * 8;
            uint32_t a[2][4];
            #pragma unroll
            for (int mi = 0; mi < 2; mi++) {
                const int mb = mi*16;
                a[mi][0] = As[buf][mb + grp    ][kb + tig];
                a[mi][1] = As[buf][mb + grp + 8][kb + tig];
                a[mi][2] = As[buf][mb + grp    ][kb + tig + 4];
                a[mi][3] = As[buf][mb + grp + 8][kb + tig + 4];
            }
            uint32_t bfr[2][2];
            #pragma unroll
            for (int ni = 0; ni < 2; ni++) {
                const int nb = wid*16 + ni*8;
                bfr[ni][0] = Bsm[buf][kb + tig    ][nb + grp];
                bfr[ni][1] = Bsm[buf][kb + tig + 4][nb + grp];
            }
            #pragma unroll
            for (int mi = 0; mi < 2; mi++)
                #pragma unroll
                for (int ni = 0; ni < 2; ni++)
                    mma_tf32(acc[mi][ni][0], acc[mi][ni][1], acc[mi][ni][2], acc[mi][ni][3],
                             a[mi][0], a[mi][1], a[mi][2], a[mi][3],
                             bfr[ni][0], bfr[ni][1]);
        }
        __syncthreads();
        buf ^= 1;
    }

    #pragma unroll
    for (int mi = 0; mi < 2; mi++) {
        #pragma unroll
        for (int ni = 0; ni < 2; ni++) {
            const int col = d0 + wid*16 + ni*8 + 2*tig;
            const int r0  = q0 + mi*16 + grp;
            const int r1  = r0 + 8;
            float2 lo = { acc[mi][ni][0], acc[mi][ni][1] };
            float2 hi = { acc[mi][ni][2], acc[mi][ni][3] };
            *(float2*)&out[((size_t)b*LQ + r0) * DD + col] = lo;
            *(float2*)&out[((size_t)b*LQ + r1) * DD + col] = hi;
        }
    }
}

// ---------------------------------------------------------------------------
extern "C" void kernel_launch(void* const* d_in, const int* in_sizes, int n_in,
                              void* d_out, int out_size)
{
    const float* query = (const float*)d_in[0];
    const float* key   = (const float*)d_in[1];
    const float* value = (const float*)d_in[2];
    const float* Wq    = (const float*)d_in[3];
    const float* bq    = (const float*)d_in[4];
    const float* Wk    = (const float*)d_in[5];
    const float* bk    = (const float*)d_in[6];
    const float* Wv    = (const float*)d_in[7];
    const float* bv    = (const float*)d_in[8];
    const float* Ws    = (const float*)d_in[9];
    const float* bs    = (const float*)d_in[10];

    float* att = (float*)d_out;                  // [B,LQ,D]
    float* wts = att + (size_t)BB * LQ * DD;     // [B,LQ,LK]

    proj_kernel<<<dim3(DD/128, (BB*LQ)/64, 3), 256>>>(
        query, key, value, Wq, bq, Wk, bk, Wv, bv);

    // reset score tile counter (graph-capturable memset node)
    void* ctr_addr = nullptr;
    cudaGetSymbolAddress(&ctr_addr, g_tile_ctr);
    cudaMemsetAsync(ctr_addr, 0, sizeof(unsigned));

    score_kernel<<<296, 256>>>(Ws, bs);

    softmax_kernel<<<BB*LQ, 256>>>(wts);

    av_kernel<<<dim3(DD/128, LQ/32, BB), 256>>>(wts, att);
}